// round 3
// baseline (speedup 1.0000x reference)
#include <cuda_runtime.h>
#include <math.h>

#define B_   4
#define LQ   1024
#define LK   2048
#define H_   8
#define HID  256
#define D_   32
#define TEMP_INV 10.0f
#define LOG2E 1.4426950408889634f

// ---------------- scratch (device globals; no allocations) ----------------
__device__ float g_G[H_ * 12 * 12];                 // per-head bilinear form (pre-scaled by LOG2E)
__device__ float g_R[88 * HID];                     // fused Av_h @ Wo_h^T
__device__ float g_obias[HID];                      // bo + bv @ Wo^T
__device__ float g_Q[(size_t)B_ * H_ * 12 * LQ];    // Q-hat transposed [bh][c][q], c=0..11
__device__ float g_Kraw[(size_t)B_ * 11 * LK];      // raw key features transposed [b][j][k]
__device__ float g_kc[(size_t)B_ * H_ * LK];        // -beta*kn*LOG2E per head
__device__ float g_lp[(size_t)B_ * LQ * LK];        // log2(clip(pi,1e-9))
__device__ float g_cr[(size_t)B_ * LQ * 88];        // ctxRaw

__device__ __forceinline__ float sigmoidf_(float x) { return 1.f / (1.f + expf(-x)); }

// fast exp2 via MUFU (no __exp2f intrinsic exists; go straight to EX2)
__device__ __forceinline__ float ex2f(float x) {
    float r;
    asm("ex2.approx.ftz.f32 %0, %1;" : "=f"(r) : "f"(x));
    return r;
}

// packed fp32x2 ops (FFMA2/FADD2 — only reachable via PTX on sm_103a)
__device__ __forceinline__ void f2fma(float2 &d, float2 a, float2 b) {
    asm("fma.rn.f32x2 %0, %1, %2, %0;"
        : "+l"(reinterpret_cast<unsigned long long&>(d))
        : "l"(reinterpret_cast<unsigned long long&>(a)),
          "l"(reinterpret_cast<unsigned long long&>(b)));
}
__device__ __forceinline__ float2 f2add(float2 a, float2 b) {
    float2 d;
    asm("add.rn.f32x2 %0, %1, %2;"
        : "=l"(reinterpret_cast<unsigned long long&>(d))
        : "l"(reinterpret_cast<unsigned long long&>(a)),
          "l"(reinterpret_cast<unsigned long long&>(b)));
    return d;
}

// ---------------- P0: fold weights into G_h, R, obias ----------------
__global__ void p0_params(const float* __restrict__ Wq_s, const float* __restrict__ bq_s,
                          const float* __restrict__ Wk_s, const float* __restrict__ bk_s,
                          const float* __restrict__ Wq_w, const float* __restrict__ bq_w,
                          const float* __restrict__ Wk_w, const float* __restrict__ bk_w,
                          const float* __restrict__ Wv,   const float* __restrict__ bv,
                          const float* __restrict__ Wo,   const float* __restrict__ bo,
                          const float* __restrict__ wb)
{
    int t = threadIdx.x;
    int blk = blockIdx.x;
    if (blk == H_) {
        float acc = bo[t];
        for (int u = 0; u < HID; u++) acc += bv[u] * Wo[t * HID + u];
        g_obias[t] = acc;
        return;
    }
    int h = blk;
    float alpha = sigmoidf_(wb[0]);
    float c1 = (1.f - alpha) / sqrtf((float)D_) * LOG2E;
    float c2 = 2.f * alpha * TEMP_INV * LOG2E;

    if (t < 144) {
        int r = t / 12, c = t % 12;
        float acc = 0.f;
        if (r < 8 && c < 8) {
            for (int d = 0; d < 32; d++) acc += Wq_s[(h*32+d)*8 + r] * Wk_s[(h*32+d)*8 + c];
            acc *= c1;
        } else if (r < 8 && c == 11) {
            for (int d = 0; d < 32; d++) acc += Wq_s[(h*32+d)*8 + r] * bk_s[h*32+d];
            acc *= c1;
        } else if (r >= 8 && r < 11 && c >= 8 && c < 11) {
            for (int d = 0; d < 32; d++) acc += Wq_w[(h*32+d)*3 + (r-8)] * Wk_w[(h*32+d)*3 + (c-8)];
            acc *= c2;
        } else if (r >= 8 && r < 11 && c == 11) {
            for (int d = 0; d < 32; d++) acc += Wq_w[(h*32+d)*3 + (r-8)] * bk_w[h*32+d];
            acc *= c2;
        } else if (r == 11 && c < 8) {
            for (int d = 0; d < 32; d++) acc += bq_s[h*32+d] * Wk_s[(h*32+d)*8 + c];
            acc *= c1;
        } else if (r == 11 && c >= 8 && c < 11) {
            for (int d = 0; d < 32; d++) acc += bq_w[h*32+d] * Wk_w[(h*32+d)*3 + (c-8)];
            acc *= c2;
        } else if (r == 11 && c == 11) {
            float a1 = 0.f, a2 = 0.f;
            for (int d = 0; d < 32; d++) {
                a1 += bq_s[h*32+d] * bk_s[h*32+d];
                a2 += bq_w[h*32+d] * bk_w[h*32+d];
            }
            acc = c1 * a1 + c2 * a2;
        }
        g_G[(h*12 + r)*12 + c] = acc;
    }
    float wo[32];
    #pragma unroll
    for (int d = 0; d < 32; d++) wo[d] = Wo[t * HID + h*32 + d];
    for (int j = 0; j < 11; j++) {
        float acc = 0.f;
        #pragma unroll
        for (int d = 0; d < 32; d++) acc += Wv[(h*32+d)*11 + j] * wo[d];
        g_R[(h*11 + j) * HID + t] = acc;
    }
}

// ---------------- P1q: build Q-hat (transposed, LOG2E-scaled) ----------------
__global__ void __launch_bounds__(128)
p1_q(const float* __restrict__ q_fp, const float* __restrict__ Wq_w,
     const float* __restrict__ bq_w, const float* __restrict__ wb)
{
    __shared__ float Gs[H_ * 144];
    __shared__ float Ws[HID * 3];
    __shared__ float Bs[HID];
    int t = threadIdx.x;
    for (int i = t; i < H_ * 144; i += 128) Gs[i] = g_G[i];
    for (int i = t; i < HID * 3;  i += 128) Ws[i] = Wq_w[i];
    for (int i = t; i < HID;      i += 128) Bs[i] = bq_w[i];
    __syncthreads();

    float alpha = sigmoidf_(wb[0]);
    float beta2 = alpha * TEMP_INV * LOG2E;
    int idx = blockIdx.x * 128 + t;   // b*LQ + q
    int b = idx >> 10, q = idx & (LQ - 1);

    float x[11];
    #pragma unroll
    for (int j = 0; j < 11; j++) x[j] = q_fp[(size_t)idx * 11 + j];

    for (int h = 0; h < H_; h++) {
        float qn = 0.f;
        #pragma unroll 4
        for (int d = 0; d < 32; d++) {
            float s = Bs[h*32 + d];
            s += x[8]  * Ws[(h*32+d)*3 + 0];
            s += x[9]  * Ws[(h*32+d)*3 + 1];
            s += x[10] * Ws[(h*32+d)*3 + 2];
            qn += s * s;
        }
        size_t base = ((size_t)(b * H_ + h) * 12) * LQ + q;
        const float* Gh = &Gs[h * 144];
        #pragma unroll
        for (int c = 0; c < 12; c++) {
            float a = Gh[11*12 + c];
            #pragma unroll
            for (int r = 0; r < 11; r++) a += x[r] * Gh[r*12 + c];
            if (c == 11) a -= beta2 * qn;
            g_Q[base + (size_t)c * LQ] = a;
        }
    }
}

// ---------------- P1k: raw K features (transposed) + per-head kn term ----------------
__global__ void __launch_bounds__(128)
p1_k(const float* __restrict__ v_ret, const float* __restrict__ Wk_w,
     const float* __restrict__ bk_w, const float* __restrict__ wb)
{
    __shared__ float Ws[HID * 3];
    __shared__ float Bs[HID];
    int t = threadIdx.x;
    for (int i = t; i < HID * 3; i += 128) Ws[i] = Wk_w[i];
    for (int i = t; i < HID;     i += 128) Bs[i] = bk_w[i];
    __syncthreads();

    float alpha = sigmoidf_(wb[0]);
    float beta2 = alpha * TEMP_INV * LOG2E;
    int idx = blockIdx.x * 128 + t;   // b*LK + k
    int b = idx >> 11, k = idx & (LK - 1);

    float x[11];
    #pragma unroll
    for (int j = 0; j < 11; j++) x[j] = v_ret[(size_t)idx * 11 + j];

    #pragma unroll
    for (int j = 0; j < 11; j++)
        g_Kraw[((size_t)b * 11 + j) * LK + k] = x[j];

    for (int h = 0; h < H_; h++) {
        float kn = 0.f;
        #pragma unroll 4
        for (int d = 0; d < 32; d++) {
            float s = Bs[h*32 + d];
            s += x[8]  * Ws[(h*32+d)*3 + 0];
            s += x[9]  * Ws[(h*32+d)*3 + 1];
            s += x[10] * Ws[(h*32+d)*3 + 2];
            kn += s * s;
        }
        g_kc[(size_t)(b * H_ + h) * LK + k] = -beta2 * kn;
    }
}

// ---------------- P2: log2 of transport mask, once (shared by all heads) ----------------
__global__ void __launch_bounds__(256)
p_logpi(const float* __restrict__ pi)
{
    size_t i = ((size_t)blockIdx.x * 256 + threadIdx.x) * 4;
    float4 v = *(const float4*)(pi + i);
    v.x = __log2f(fmaxf(v.x, 1e-9f));
    v.y = __log2f(fmaxf(v.y, 1e-9f));
    v.z = __log2f(fmaxf(v.z, 1e-9f));
    v.w = __log2f(fmaxf(v.w, 1e-9f));
    *(float4*)(g_lp + i) = v;
}

// ---------------- main attention kernel: fp32x2 SIMT, no online max ----------------
// 256 threads = 8 tx (8 keys each) x 32 ty (2 rows each). BM=64, BN=64.
__global__ void __launch_bounds__(256, 2)
attn_kernel()
{
    __shared__ float Qs[12][64];        // rows 0..10: Q-tilde, row 11: q const (incl -b*qn)
    __shared__ float Ks[2][12][64];     // rows 0..10: raw key feats (= V), row 11: kc

    int t = threadIdx.x;
    int tx = t & 7, ty = t >> 3;
    int h = blockIdx.x, qt = blockIdx.y, b = blockIdx.z;
    int bh = b * H_ + h;
    int q0 = qt * 64;

    if (t < 192) {
        int c = t >> 4, col4 = (t & 15) * 4;
        *(float4*)&Qs[c][col4] =
            *(const float4*)&g_Q[((size_t)bh * 12 + c) * LQ + q0 + col4];
        const float* src = (c < 11)
            ? &g_Kraw[((size_t)b * 11 + c) * LK + col4]
            : &g_kc[(size_t)bh * LK + col4];
        *(float4*)&Ks[0][c][col4] = *(const float4*)src;
    }

    float2 O[2][11];
    float2 l2[2];
    #pragma unroll
    for (int i = 0; i < 2; i++) {
        l2[i] = make_float2(0.f, 0.f);
        #pragma unroll
        for (int c = 0; c < 11; c++) O[i][c] = make_float2(0.f, 0.f);
    }

    const float* lpP = g_lp + ((size_t)(b * LQ + q0 + ty * 2)) * LK + tx * 8;

    __syncthreads();

    for (int kt = 0; kt < 32; kt++) {
        int cur = kt & 1;
        int k0 = kt * 64;

        // issue lp loads now; consumed only after the QK phase (L2 latency hidden)
        float4 lp0 = *(const float4*)(lpP + k0);
        float4 lp1 = *(const float4*)(lpP + k0 + 4);
        float4 lp2v = *(const float4*)(lpP + k0 + LK);
        float4 lp3 = *(const float4*)(lpP + k0 + LK + 4);

        // stage next K tile into the other buffer
        if (kt < 31 && t < 192) {
            int kk = t >> 4, col4 = (t & 15) * 4;
            const float* src = (kk < 11)
                ? &g_Kraw[((size_t)b * 11 + kk) * LK + k0 + 64 + col4]
                : &g_kc[(size_t)bh * LK + k0 + 64 + col4];
            *(float4*)&Ks[cur ^ 1][kk][col4] = *(const float4*)src;
        }

        // ---- QK: S = Qt . k_raw  (inner dim 11), packed over key pairs ----
        float2 S[2][4];
        #pragma unroll
        for (int i = 0; i < 2; i++)
            #pragma unroll
            for (int jp = 0; jp < 4; jp++) S[i][jp] = make_float2(0.f, 0.f);

        #pragma unroll
        for (int kk = 0; kk < 11; kk++) {
            float2 q = *(const float2*)&Qs[kk][ty * 2];
            float4 ka = *(const float4*)&Ks[cur][kk][tx * 8];
            float4 kb = *(const float4*)&Ks[cur][kk][tx * 8 + 4];
            float2 k20 = make_float2(ka.x, ka.y);
            float2 k21 = make_float2(ka.z, ka.w);
            float2 k22 = make_float2(kb.x, kb.y);
            float2 k23 = make_float2(kb.z, kb.w);
            float2 qd0 = make_float2(q.x, q.x);
            float2 qd1 = make_float2(q.y, q.y);
            f2fma(S[0][0], qd0, k20); f2fma(S[0][1], qd0, k21);
            f2fma(S[0][2], qd0, k22); f2fma(S[0][3], qd0, k23);
            f2fma(S[1][0], qd1, k20); f2fma(S[1][1], qd1, k21);
            f2fma(S[1][2], qd1, k22); f2fma(S[1][3], qd1, k23);
        }

        // ---- add per-row const + per-key const + log2(pi) ----
        {
            float4 kca = *(const float4*)&Ks[cur][11][tx * 8];
            float4 kcb = *(const float4*)&Ks[cur][11][tx * 8 + 4];
            float2 kc2[4] = { make_float2(kca.x, kca.y), make_float2(kca.z, kca.w),
                              make_float2(kcb.x, kcb.y), make_float2(kcb.z, kcb.w) };
            float2 q11 = *(const float2*)&Qs[11][ty * 2];
            float2 lpr0[4] = { make_float2(lp0.x, lp0.y), make_float2(lp0.z, lp0.w),
                               make_float2(lp1.x, lp1.y), make_float2(lp1.z, lp1.w) };
            float2 lpr1[4] = { make_float2(lp2v.x, lp2v.y), make_float2(lp2v.z, lp2v.w),
                               make_float2(lp3.x, lp3.y), make_float2(lp3.z, lp3.w) };
            float2 q11d0 = make_float2(q11.x, q11.x);
            float2 q11d1 = make_float2(q11.y, q11.y);
            #pragma unroll
            for (int jp = 0; jp < 4; jp++) {
                float2 c0 = f2add(kc2[jp], q11d0);
                float2 c1 = f2add(kc2[jp], q11d1);
                S[0][jp] = f2add(S[0][jp], f2add(lpr0[jp], c0));
                S[1][jp] = f2add(S[1][jp], f2add(lpr1[jp], c1));
            }
        }

        // ---- exp2 (logits bounded above by ~1: wave<=0, logpi<=0, spatial tiny) ----
        #pragma unroll
        for (int i = 0; i < 2; i++)
            #pragma unroll
            for (int jp = 0; jp < 4; jp++) {
                S[i][jp].x = ex2f(S[i][jp].x);
                S[i][jp].y = ex2f(S[i][jp].y);
                l2[i] = f2add(l2[i], S[i][jp]);
            }

        // ---- PV: O += P . v_raw  (V tile == K tile rows 0..10) ----
        #pragma unroll
        for (int c = 0; c < 11; c++) {
            float4 va = *(const float4*)&Ks[cur][c][tx * 8];
            float4 vb = *(const float4*)&Ks[cur][c][tx * 8 + 4];
            float2 v0 = make_float2(va.x, va.y);
            float2 v1 = make_float2(va.z, va.w);
            float2 v2 = make_float2(vb.x, vb.y);
            float2 v3 = make_float2(vb.z, vb.w);
            f2fma(O[0][c], S[0][0], v0); f2fma(O[0][c], S[0][1], v1);
            f2fma(O[0][c], S[0][2], v2); f2fma(O[0][c], S[0][3], v3);
            f2fma(O[1][c], S[1][0], v0); f2fma(O[1][c], S[1][1], v1);
            f2fma(O[1][c], S[1][2], v2); f2fma(O[1][c], S[1][3], v3);
        }

        __syncthreads();
    }

    // ---- reduce across the 8 tx lanes, normalize, store ----
    #pragma unroll
    for (int i = 0; i < 2; i++) {
        float l = l2[i].x + l2[i].y;
        l += __shfl_xor_sync(0xffffffffu, l, 1);
        l += __shfl_xor_sync(0xffffffffu, l, 2);
        l += __shfl_xor_sync(0xffffffffu, l, 4);
        float inv = 1.0f / l;
        size_t base = ((size_t)(b * LQ + q0 + ty * 2 + i)) * 88 + h * 11;
        #pragma unroll
        for (int c = 0; c < 11; c++) {
            float o = O[i][c].x + O[i][c].y;
            o += __shfl_xor_sync(0xffffffffu, o, 1);
            o += __shfl_xor_sync(0xffffffffu, o, 2);
            o += __shfl_xor_sync(0xffffffffu, o, 4);
            if (tx == 0) g_cr[base + c] = o * inv;
        }
    }
}

// ---------------- epilogue: out = ctxRaw(4096x88) @ R(88x256) + obias ----------------
__global__ void __launch_bounds__(256)
epilogue_kernel(float* __restrict__ out)
{
    __shared__ float crsT[88][32];
    int t = threadIdx.x;
    int row0 = blockIdx.x * 32;

    for (int i = t; i < 32 * 88; i += 256) {
        int r = i / 88, j = i % 88;
        crsT[j][r] = g_cr[(size_t)(row0 + r) * 88 + j];
    }
    __syncthreads();

    float acc[32];
    #pragma unroll
    for (int r = 0; r < 32; r++) acc[r] = 0.f;

    #pragma unroll 4
    for (int j = 0; j < 88; j++) {
        float rv = g_R[j * HID + t];
        #pragma unroll
        for (int r = 0; r < 32; r += 4) {
            float4 cv = *(const float4*)&crsT[j][r];
            acc[r]     += cv.x * rv;
            acc[r + 1] += cv.y * rv;
            acc[r + 2] += cv.z * rv;
            acc[r + 3] += cv.w * rv;
        }
    }

    float ob = g_obias[t];
    for (int r = 0; r < 32; r++)
        out[(size_t)(row0 + r) * HID + t] = acc[r] + ob;
}

// ---------------- launch ----------------
extern "C" void kernel_launch(void* const* d_in, const int* in_sizes, int n_in,
                              void* d_out, int out_size)
{
    const float* q_fp  = (const float*)d_in[0];
    const float* v_ret = (const float*)d_in[1];
    const float* pi    = (const float*)d_in[2];
    const float* Wq_s  = (const float*)d_in[3];
    const float* bq_s  = (const float*)d_in[4];
    const float* Wk_s  = (const float*)d_in[5];
    const float* bk_s  = (const float*)d_in[6];
    const float* Wq_w  = (const float*)d_in[7];
    const float* bq_w  = (const float*)d_in[8];
    const float* Wk_w  = (const float*)d_in[9];
    const float* bk_w  = (const float*)d_in[10];
    const float* Wv    = (const float*)d_in[11];
    const float* bv    = (const float*)d_in[12];
    const float* Wo    = (const float*)d_in[13];
    const float* bo    = (const float*)d_in[14];
    const float* wb    = (const float*)d_in[15];
    float* out = (float*)d_out;

    p0_params<<<H_ + 1, 256>>>(Wq_s, bq_s, Wk_s, bk_s, Wq_w, bq_w, Wk_w, bk_w,
                               Wv, bv, Wo, bo, wb);
    p1_q<<<(B_ * LQ) / 128, 128>>>(q_fp, Wq_w, bq_w, wb);
    p1_k<<<(B_ * LK) / 128, 128>>>(v_ret, Wk_w, bk_w, wb);
    p_logpi<<<(B_ * LQ * LK) / 1024, 256>>>(pi);
    dim3 g(H_, LQ / 64, B_);
    attn_kernel<<<g, 256>>>();
    epilogue_kernel<<<(B_ * LQ) / 32, 256>>>(out);
}

// round 4
// speedup vs baseline: 1.9720x; 1.9720x over previous
#include <cuda_runtime.h>
#include <math.h>

#define B_   4
#define LQ   1024
#define LK   2048
#define H_   8
#define HID  256
#define D_   32
#define TEMP_INV 10.0f
#define LOG2E 1.4426950408889634f

// ---------------- scratch (device globals; no allocations) ----------------
__device__ float g_G[H_ * 12 * 12];                 // per-head bilinear form (LOG2E-scaled)
__device__ float g_R[88 * HID];                     // fused Av_h @ Wo_h^T
__device__ float g_obias[HID];                      // bo + bv @ Wo^T
__device__ float g_Q[(size_t)B_ * H_ * 11 * LQ];    // Q-hat transposed [bh][c][q], c=0..10
__device__ float g_Kraw[(size_t)B_ * 11 * LK];      // raw key features transposed [b][j][k]
__device__ float g_kc[(size_t)B_ * H_ * LK];        // -beta*kn*LOG2E per head
__device__ float g_lp[(size_t)B_ * LQ * LK];        // log2(clip(pi,1e-9))
__device__ float g_cr[(size_t)B_ * LQ * 88];        // ctxRaw

__device__ __forceinline__ float sigmoidf_(float x) { return 1.f / (1.f + expf(-x)); }

// fast exp2 via MUFU
__device__ __forceinline__ float ex2f(float x) {
    float r;
    asm("ex2.approx.ftz.f32 %0, %1;" : "=f"(r) : "f"(x));
    return r;
}

// ---------------- P0: fold weights into G_h, R, obias ----------------
__global__ void p0_params(const float* __restrict__ Wq_s, const float* __restrict__ bq_s,
                          const float* __restrict__ Wk_s, const float* __restrict__ bk_s,
                          const float* __restrict__ Wq_w, const float* __restrict__ bq_w,
                          const float* __restrict__ Wk_w, const float* __restrict__ bk_w,
                          const float* __restrict__ Wv,   const float* __restrict__ bv,
                          const float* __restrict__ Wo,   const float* __restrict__ bo,
                          const float* __restrict__ wb)
{
    int t = threadIdx.x;
    int blk = blockIdx.x;
    if (blk == H_) {
        float acc = bo[t];
        for (int u = 0; u < HID; u++) acc += bv[u] * Wo[t * HID + u];
        g_obias[t] = acc;
        return;
    }
    int h = blk;
    float alpha = sigmoidf_(wb[0]);
    float c1 = (1.f - alpha) / sqrtf((float)D_) * LOG2E;
    float c2 = 2.f * alpha * TEMP_INV * LOG2E;

    if (t < 144) {
        int r = t / 12, c = t % 12;
        float acc = 0.f;
        if (r < 8 && c < 8) {
            for (int d = 0; d < 32; d++) acc += Wq_s[(h*32+d)*8 + r] * Wk_s[(h*32+d)*8 + c];
            acc *= c1;
        } else if (r < 8 && c == 11) {
            for (int d = 0; d < 32; d++) acc += Wq_s[(h*32+d)*8 + r] * bk_s[h*32+d];
            acc *= c1;
        } else if (r >= 8 && r < 11 && c >= 8 && c < 11) {
            for (int d = 0; d < 32; d++) acc += Wq_w[(h*32+d)*3 + (r-8)] * Wk_w[(h*32+d)*3 + (c-8)];
            acc *= c2;
        } else if (r >= 8 && r < 11 && c == 11) {
            for (int d = 0; d < 32; d++) acc += Wq_w[(h*32+d)*3 + (r-8)] * bk_w[h*32+d];
            acc *= c2;
        } else if (r == 11 && c < 8) {
            for (int d = 0; d < 32; d++) acc += bq_s[h*32+d] * Wk_s[(h*32+d)*8 + c];
            acc *= c1;
        } else if (r == 11 && c >= 8 && c < 11) {
            for (int d = 0; d < 32; d++) acc += bq_w[h*32+d] * Wk_w[(h*32+d)*3 + (c-8)];
            acc *= c2;
        } else if (r == 11 && c == 11) {
            float a1 = 0.f, a2 = 0.f;
            for (int d = 0; d < 32; d++) {
                a1 += bq_s[h*32+d] * bk_s[h*32+d];
                a2 += bq_w[h*32+d] * bk_w[h*32+d];
            }
            acc = c1 * a1 + c2 * a2;
        }
        g_G[(h*12 + r)*12 + c] = acc;
    }
    float wo[32];
    #pragma unroll
    for (int d = 0; d < 32; d++) wo[d] = Wo[t * HID + h*32 + d];
    for (int j = 0; j < 11; j++) {
        float acc = 0.f;
        #pragma unroll
        for (int d = 0; d < 32; d++) acc += Wv[(h*32+d)*11 + j] * wo[d];
        g_R[(h*11 + j) * HID + t] = acc;
    }
}

// ---------------- P1q: build Q-hat (11 rows; per-row const dropped — softmax shift-invariant) ----------------
__global__ void __launch_bounds__(128)
p1_q(const float* __restrict__ q_fp)
{
    __shared__ float Gs[H_ * 144];
    int t = threadIdx.x;
    for (int i = t; i < H_ * 144; i += 128) Gs[i] = g_G[i];
    __syncthreads();

    int idx = blockIdx.x * 128 + t;   // b*LQ + q
    int b = idx >> 10, q = idx & (LQ - 1);

    float x[11];
    #pragma unroll
    for (int j = 0; j < 11; j++) x[j] = q_fp[(size_t)idx * 11 + j];

    for (int h = 0; h < H_; h++) {
        size_t base = ((size_t)(b * H_ + h) * 11) * LQ + q;
        const float* Gh = &Gs[h * 144];
        #pragma unroll
        for (int c = 0; c < 11; c++) {
            float a = Gh[11*12 + c];      // bias-row contribution (varies with c → kept)
            #pragma unroll
            for (int r = 0; r < 11; r++) a += x[r] * Gh[r*12 + c];
            g_Q[base + (size_t)c * LQ] = a;
        }
    }
}

// ---------------- P1k: raw K features (transposed) + per-head kn term ----------------
__global__ void __launch_bounds__(128)
p1_k(const float* __restrict__ v_ret, const float* __restrict__ Wk_w,
     const float* __restrict__ bk_w, const float* __restrict__ wb)
{
    __shared__ float Ws[HID * 3];
    __shared__ float Bs[HID];
    int t = threadIdx.x;
    for (int i = t; i < HID * 3; i += 128) Ws[i] = Wk_w[i];
    for (int i = t; i < HID;     i += 128) Bs[i] = bk_w[i];
    __syncthreads();

    float alpha = sigmoidf_(wb[0]);
    float beta2 = alpha * TEMP_INV * LOG2E;
    int idx = blockIdx.x * 128 + t;   // b*LK + k
    int b = idx >> 11, k = idx & (LK - 1);

    float x[11];
    #pragma unroll
    for (int j = 0; j < 11; j++) x[j] = v_ret[(size_t)idx * 11 + j];

    #pragma unroll
    for (int j = 0; j < 11; j++)
        g_Kraw[((size_t)b * 11 + j) * LK + k] = x[j];

    for (int h = 0; h < H_; h++) {
        float kn = 0.f;
        #pragma unroll 4
        for (int d = 0; d < 32; d++) {
            float s = Bs[h*32 + d];
            s += x[8]  * Ws[(h*32+d)*3 + 0];
            s += x[9]  * Ws[(h*32+d)*3 + 1];
            s += x[10] * Ws[(h*32+d)*3 + 2];
            kn += s * s;
        }
        g_kc[(size_t)(b * H_ + h) * LK + k] = -beta2 * kn;
    }
}

// ---------------- P2: log2 of transport mask, once (shared by all heads) ----------------
__global__ void __launch_bounds__(256)
p_logpi(const float* __restrict__ pi)
{
    size_t i = ((size_t)blockIdx.x * 256 + threadIdx.x) * 4;
    float4 v = *(const float4*)(pi + i);
    v.x = __log2f(fmaxf(v.x, 1e-9f));
    v.y = __log2f(fmaxf(v.y, 1e-9f));
    v.z = __log2f(fmaxf(v.z, 1e-9f));
    v.w = __log2f(fmaxf(v.w, 1e-9f));
    *(float4*)(g_lp + i) = v;
}

// ---------------- main attention kernel: scalar fp32, no online max ----------------
// 256 threads = 16 tx (4 keys) x 16 ty (4 rows). BM=BN=64. Double-buffered K tile.
__global__ void __launch_bounds__(256, 2)
attn_kernel()
{
    __shared__ float Qs[11][64];        // Q-tilde rows 0..10
    __shared__ float Ks[2][12][64];     // rows 0..10: raw key feats (= V), row 11: kc

    int t = threadIdx.x;
    int tx = t & 15, ty = t >> 4;
    int h = blockIdx.x, qt = blockIdx.y, b = blockIdx.z;
    int bh = b * H_ + h;
    int q0 = qt * 64;

    if (t < 176) {
        int c = t >> 4, col4 = (t & 15) * 4;
        *(float4*)&Qs[c][col4] =
            *(const float4*)&g_Q[((size_t)bh * 11 + c) * LQ + q0 + col4];
    }
    if (t < 192) {
        int c = t >> 4, col4 = (t & 15) * 4;
        const float* src = (c < 11)
            ? &g_Kraw[((size_t)b * 11 + c) * LK + col4]
            : &g_kc[(size_t)bh * LK + col4];
        *(float4*)&Ks[0][c][col4] = *(const float4*)src;
    }

    float O[4][11];
    float l[4];
    #pragma unroll
    for (int i = 0; i < 4; i++) {
        l[i] = 0.f;
        #pragma unroll
        for (int c = 0; c < 11; c++) O[i][c] = 0.f;
    }

    const float* lpP = g_lp + ((size_t)(b * LQ + q0 + ty * 4)) * LK + tx * 4;

    __syncthreads();

    for (int kt = 0; kt < 32; kt++) {
        int cur = kt & 1;
        int k0 = kt * 64;

        // prefetch log2(pi) tile (consumed after QK — L2 latency hidden)
        float4 pv0 = *(const float4*)(lpP + k0);
        float4 pv1 = *(const float4*)(lpP + (size_t)LK + k0);
        float4 pv2 = *(const float4*)(lpP + (size_t)2 * LK + k0);
        float4 pv3 = *(const float4*)(lpP + (size_t)3 * LK + k0);

        // stage next K tile into the other buffer
        if (kt < 31 && t < 192) {
            int c = t >> 4, col4 = (t & 15) * 4;
            const float* src = (c < 11)
                ? &g_Kraw[((size_t)b * 11 + c) * LK + k0 + 64 + col4]
                : &g_kc[(size_t)bh * LK + k0 + 64 + col4];
            *(float4*)&Ks[cur ^ 1][c][col4] = *(const float4*)src;
        }

        // ---- QK: S = Qt . k_raw  (inner dim 11) ----
        float S[4][4];
        #pragma unroll
        for (int i = 0; i < 4; i++)
            #pragma unroll
            for (int j = 0; j < 4; j++) S[i][j] = 0.f;

        #pragma unroll
        for (int kk = 0; kk < 11; kk++) {
            float4 a4 = *(const float4*)&Qs[kk][ty * 4];
            float4 b4 = *(const float4*)&Ks[cur][kk][tx * 4];
            float av[4] = {a4.x, a4.y, a4.z, a4.w};
            float bw[4] = {b4.x, b4.y, b4.z, b4.w};
            #pragma unroll
            for (int i = 0; i < 4; i++)
                #pragma unroll
                for (int j = 0; j < 4; j++) S[i][j] += av[i] * bw[j];
        }

        // ---- + kc + log2(pi), exp2, accumulate l ----
        {
            float4 kc4 = *(const float4*)&Ks[cur][11][tx * 4];
            float kcv[4] = {kc4.x, kc4.y, kc4.z, kc4.w};
            float pr[4][4] = {{pv0.x, pv0.y, pv0.z, pv0.w},
                              {pv1.x, pv1.y, pv1.z, pv1.w},
                              {pv2.x, pv2.y, pv2.z, pv2.w},
                              {pv3.x, pv3.y, pv3.z, pv3.w}};
            #pragma unroll
            for (int i = 0; i < 4; i++) {
                #pragma unroll
                for (int j = 0; j < 4; j++) {
                    S[i][j] = ex2f(S[i][j] + kcv[j] + pr[i][j]);
                    l[i] += S[i][j];
                }
            }
        }

        // ---- PV: O += P . v_raw  (V tile == K tile rows 0..10) ----
        #pragma unroll
        for (int c = 0; c < 11; c++) {
            float4 v4 = *(const float4*)&Ks[cur][c][tx * 4];
            float vv[4] = {v4.x, v4.y, v4.z, v4.w};
            #pragma unroll
            for (int i = 0; i < 4; i++) {
                O[i][c] += S[i][0] * vv[0] + S[i][1] * vv[1]
                         + S[i][2] * vv[2] + S[i][3] * vv[3];
            }
        }

        __syncthreads();
    }

    // ---- reduce across the 16 tx lanes, normalize, store ----
    #pragma unroll
    for (int i = 0; i < 4; i++) {
        l[i] += __shfl_xor_sync(0xffffffffu, l[i], 1);
        l[i] += __shfl_xor_sync(0xffffffffu, l[i], 2);
        l[i] += __shfl_xor_sync(0xffffffffu, l[i], 4);
        l[i] += __shfl_xor_sync(0xffffffffu, l[i], 8);
        #pragma unroll
        for (int c = 0; c < 11; c++) {
            O[i][c] += __shfl_xor_sync(0xffffffffu, O[i][c], 1);
            O[i][c] += __shfl_xor_sync(0xffffffffu, O[i][c], 2);
            O[i][c] += __shfl_xor_sync(0xffffffffu, O[i][c], 4);
            O[i][c] += __shfl_xor_sync(0xffffffffu, O[i][c], 8);
        }
    }

    if (tx == 0) {
        #pragma unroll
        for (int i = 0; i < 4; i++) {
            float inv = 1.0f / l[i];
            size_t base = ((size_t)(b * LQ + q0 + ty * 4 + i)) * 88 + h * 11;
            #pragma unroll
            for (int c = 0; c < 11; c++) g_cr[base + c] = O[i][c] * inv;
        }
    }
}

// ---------------- epilogue: out = ctxRaw(4096x88) @ R(88x256) + obias ----------------
__global__ void __launch_bounds__(256)
epilogue_kernel(float* __restrict__ out)
{
    __shared__ float crsT[88][32];
    int t = threadIdx.x;
    int row0 = blockIdx.x * 32;

    for (int i = t; i < 32 * 88; i += 256) {
        int r = i / 88, j = i % 88;
        crsT[j][r] = g_cr[(size_t)(row0 + r) * 88 + j];
    }
    __syncthreads();

    float acc[32];
    #pragma unroll
    for (int r = 0; r < 32; r++) acc[r] = 0.f;

    #pragma unroll 4
    for (int j = 0; j < 88; j++) {
        float rv = g_R[j * HID + t];
        #pragma unroll
        for (int r = 0; r < 32; r += 4) {
            float4 cv = *(const float4*)&crsT[j][r];
            acc[r]     += cv.x * rv;
            acc[r + 1] += cv.y * rv;
            acc[r + 2] += cv.z * rv;
            acc[r + 3] += cv.w * rv;
        }
    }

    float ob = g_obias[t];
    for (int r = 0; r < 32; r++)
        out[(size_t)(row0 + r) * HID + t] = acc[r] + ob;
}

// ---------------- launch ----------------
extern "C" void kernel_launch(void* const* d_in, const int* in_sizes, int n_in,
                              void* d_out, int out_size)
{
    const float* q_fp  = (const float*)d_in[0];
    const float* v_ret = (const float*)d_in[1];
    const float* pi    = (const float*)d_in[2];
    const float* Wq_s  = (const float*)d_in[3];
    const float* bq_s  = (const float*)d_in[4];
    const float* Wk_s  = (const float*)d_in[5];
    const float* bk_s  = (const float*)d_in[6];
    const float* Wq_w  = (const float*)d_in[7];
    const float* bq_w  = (const float*)d_in[8];
    const float* Wk_w  = (const float*)d_in[9];
    const float* bk_w  = (const float*)d_in[10];
    const float* Wv    = (const float*)d_in[11];
    const float* bv    = (const float*)d_in[12];
    const float* Wo    = (const float*)d_in[13];
    const float* bo    = (const float*)d_in[14];
    const float* wb    = (const float*)d_in[15];
    float* out = (float*)d_out;

    p0_params<<<H_ + 1, 256>>>(Wq_s, bq_s, Wk_s, bk_s, Wq_w, bq_w, Wk_w, bk_w,
                               Wv, bv, Wo, bo, wb);
    p1_q<<<(B_ * LQ) / 128, 128>>>(q_fp);
    p1_k<<<(B_ * LK) / 128, 128>>>(v_ret, Wk_w, bk_w, wb);
    p_logpi<<<(B_ * LQ * LK) / 1024, 256>>>(pi);
    dim3 g(H_, LQ / 64, B_);
    attn_kernel<<<g, 256>>>();
    epilogue_kernel<<<(B_ * LQ) / 32, 256>>>(out);
}

// round 5
// speedup vs baseline: 2.1215x; 1.0758x over previous
#include <cuda_runtime.h>
#include <cuda_fp16.h>
#include <math.h>

#define B_   4
#define LQ   1024
#define LK   2048
#define H_   8
#define HID  256
#define D_   32
#define TEMP_INV 10.0f
#define LOG2E 1.4426950408889634f

// ---------------- scratch (device globals; no allocations) ----------------
__device__ float g_G[H_ * 12 * 12];                 // per-head bilinear form (LOG2E-scaled)
__device__ float g_R[88 * HID];                     // fused Av_h @ Wo_h^T
__device__ float g_obias[HID];                      // bo + bv @ Wo^T
__device__ float g_Q[(size_t)B_ * H_ * 11 * LQ];    // Q-hat transposed [bh][c][q], c=0..10
__device__ float g_Kraw[(size_t)B_ * 11 * LK];      // raw key features transposed [b][j][k]
__device__ float g_kc[(size_t)B_ * H_ * LK];        // -beta*kn*LOG2E per head
__device__ __half g_lp[(size_t)B_ * LQ * LK];       // log2(clip(pi,1e-9)) in fp16
__device__ float g_cr[(size_t)B_ * LQ * 88];        // ctxRaw

__device__ __forceinline__ float sigmoidf_(float x) { return 1.f / (1.f + expf(-x)); }

// fast exp2 via MUFU
__device__ __forceinline__ float ex2f(float x) {
    float r;
    asm("ex2.approx.ftz.f32 %0, %1;" : "=f"(r) : "f"(x));
    return r;
}

// ---------------- P0: fold weights into G_h, R, obias ----------------
__global__ void p0_params(const float* __restrict__ Wq_s, const float* __restrict__ bq_s,
                          const float* __restrict__ Wk_s, const float* __restrict__ bk_s,
                          const float* __restrict__ Wq_w, const float* __restrict__ bq_w,
                          const float* __restrict__ Wk_w, const float* __restrict__ bk_w,
                          const float* __restrict__ Wv,   const float* __restrict__ bv,
                          const float* __restrict__ Wo,   const float* __restrict__ bo,
                          const float* __restrict__ wb)
{
    int t = threadIdx.x;
    int blk = blockIdx.x;
    if (blk == H_) {
        float acc = bo[t];
        for (int u = 0; u < HID; u++) acc += bv[u] * Wo[t * HID + u];
        g_obias[t] = acc;
        return;
    }
    int h = blk;
    float alpha = sigmoidf_(wb[0]);
    float c1 = (1.f - alpha) / sqrtf((float)D_) * LOG2E;
    float c2 = 2.f * alpha * TEMP_INV * LOG2E;

    if (t < 144) {
        int r = t / 12, c = t % 12;
        float acc = 0.f;
        if (r < 8 && c < 8) {
            for (int d = 0; d < 32; d++) acc += Wq_s[(h*32+d)*8 + r] * Wk_s[(h*32+d)*8 + c];
            acc *= c1;
        } else if (r < 8 && c == 11) {
            for (int d = 0; d < 32; d++) acc += Wq_s[(h*32+d)*8 + r] * bk_s[h*32+d];
            acc *= c1;
        } else if (r >= 8 && r < 11 && c >= 8 && c < 11) {
            for (int d = 0; d < 32; d++) acc += Wq_w[(h*32+d)*3 + (r-8)] * Wk_w[(h*32+d)*3 + (c-8)];
            acc *= c2;
        } else if (r >= 8 && r < 11 && c == 11) {
            for (int d = 0; d < 32; d++) acc += Wq_w[(h*32+d)*3 + (r-8)] * bk_w[h*32+d];
            acc *= c2;
        } else if (r == 11 && c < 8) {
            for (int d = 0; d < 32; d++) acc += bq_s[h*32+d] * Wk_s[(h*32+d)*8 + c];
            acc *= c1;
        } else if (r == 11 && c >= 8 && c < 11) {
            for (int d = 0; d < 32; d++) acc += bq_w[h*32+d] * Wk_w[(h*32+d)*3 + (c-8)];
            acc *= c2;
        } else if (r == 11 && c == 11) {
            float a1 = 0.f, a2 = 0.f;
            for (int d = 0; d < 32; d++) {
                a1 += bq_s[h*32+d] * bk_s[h*32+d];
                a2 += bq_w[h*32+d] * bk_w[h*32+d];
            }
            acc = c1 * a1 + c2 * a2;
        }
        g_G[(h*12 + r)*12 + c] = acc;
    }
    float wo[32];
    #pragma unroll
    for (int d = 0; d < 32; d++) wo[d] = Wo[t * HID + h*32 + d];
    for (int j = 0; j < 11; j++) {
        float acc = 0.f;
        #pragma unroll
        for (int d = 0; d < 32; d++) acc += Wv[(h*32+d)*11 + j] * wo[d];
        g_R[(h*11 + j) * HID + t] = acc;
    }
}

// ---------------- P1q: build Q-hat (11 rows; per-row const dropped — softmax shift-invariant) ----------------
__global__ void __launch_bounds__(128)
p1_q(const float* __restrict__ q_fp)
{
    __shared__ float Gs[H_ * 144];
    int t = threadIdx.x;
    for (int i = t; i < H_ * 144; i += 128) Gs[i] = g_G[i];
    __syncthreads();

    int idx = blockIdx.x * 128 + t;   // b*LQ + q
    int b = idx >> 10, q = idx & (LQ - 1);

    float x[11];
    #pragma unroll
    for (int j = 0; j < 11; j++) x[j] = q_fp[(size_t)idx * 11 + j];

    for (int h = 0; h < H_; h++) {
        size_t base = ((size_t)(b * H_ + h) * 11) * LQ + q;
        const float* Gh = &Gs[h * 144];
        #pragma unroll
        for (int c = 0; c < 11; c++) {
            float a = Gh[11*12 + c];
            #pragma unroll
            for (int r = 0; r < 11; r++) a += x[r] * Gh[r*12 + c];
            g_Q[base + (size_t)c * LQ] = a;
        }
    }
}

// ---------------- P1k: raw K features (transposed) + per-head kn term ----------------
__global__ void __launch_bounds__(128)
p1_k(const float* __restrict__ v_ret, const float* __restrict__ Wk_w,
     const float* __restrict__ bk_w, const float* __restrict__ wb)
{
    __shared__ float Ws[HID * 3];
    __shared__ float Bs[HID];
    int t = threadIdx.x;
    for (int i = t; i < HID * 3; i += 128) Ws[i] = Wk_w[i];
    for (int i = t; i < HID;     i += 128) Bs[i] = bk_w[i];
    __syncthreads();

    float alpha = sigmoidf_(wb[0]);
    float beta2 = alpha * TEMP_INV * LOG2E;
    int idx = blockIdx.x * 128 + t;   // b*LK + k
    int b = idx >> 11, k = idx & (LK - 1);

    float x[11];
    #pragma unroll
    for (int j = 0; j < 11; j++) x[j] = v_ret[(size_t)idx * 11 + j];

    #pragma unroll
    for (int j = 0; j < 11; j++)
        g_Kraw[((size_t)b * 11 + j) * LK + k] = x[j];

    for (int h = 0; h < H_; h++) {
        float kn = 0.f;
        #pragma unroll 4
        for (int d = 0; d < 32; d++) {
            float s = Bs[h*32 + d];
            s += x[8]  * Ws[(h*32+d)*3 + 0];
            s += x[9]  * Ws[(h*32+d)*3 + 1];
            s += x[10] * Ws[(h*32+d)*3 + 2];
            kn += s * s;
        }
        g_kc[(size_t)(b * H_ + h) * LK + k] = -beta2 * kn;
    }
}

// ---------------- P2: log2 of transport mask -> fp16, once (shared by all heads) ----------------
__global__ void __launch_bounds__(256)
p_logpi(const float* __restrict__ pi)
{
    size_t i = ((size_t)blockIdx.x * 256 + threadIdx.x) * 4;
    float4 v = *(const float4*)(pi + i);
    __half2 h0 = __floats2half2_rn(__log2f(fmaxf(v.x, 1e-9f)),
                                   __log2f(fmaxf(v.y, 1e-9f)));
    __half2 h1 = __floats2half2_rn(__log2f(fmaxf(v.z, 1e-9f)),
                                   __log2f(fmaxf(v.w, 1e-9f)));
    uint2 pk;
    pk.x = *(unsigned*)&h0;
    pk.y = *(unsigned*)&h1;
    *(uint2*)(g_lp + i) = pk;
}

// ---------------- main attention kernel: scalar fp32, no online max ----------------
// 256 threads = 16 tx (4 keys) x 16 ty (4 rows). BM=BN=64. Double-buffered K tile.
__global__ void __launch_bounds__(256, 2)
attn_kernel()
{
    __shared__ float Qs[11][64];        // Q-tilde rows 0..10
    __shared__ float Ks[2][12][64];     // rows 0..10: raw key feats (= V), row 11: kc

    int t = threadIdx.x;
    int tx = t & 15, ty = t >> 4;
    int h = blockIdx.x, qt = blockIdx.y, b = blockIdx.z;
    int bh = b * H_ + h;
    int q0 = qt * 64;

    if (t < 176) {
        int c = t >> 4, col4 = (t & 15) * 4;
        *(float4*)&Qs[c][col4] =
            *(const float4*)&g_Q[((size_t)bh * 11 + c) * LQ + q0 + col4];
    }
    if (t < 192) {
        int c = t >> 4, col4 = (t & 15) * 4;
        const float* src = (c < 11)
            ? &g_Kraw[((size_t)b * 11 + c) * LK + col4]
            : &g_kc[(size_t)bh * LK + col4];
        *(float4*)&Ks[0][c][col4] = *(const float4*)src;
    }

    float O[4][11];
    float l[4];
    #pragma unroll
    for (int i = 0; i < 4; i++) {
        l[i] = 0.f;
        #pragma unroll
        for (int c = 0; c < 11; c++) O[i][c] = 0.f;
    }

    const __half* lpP = g_lp + ((size_t)(b * LQ + q0 + ty * 4)) * LK + tx * 4;

    __syncthreads();

    for (int kt = 0; kt < 32; kt++) {
        int cur = kt & 1;
        int k0 = kt * 64;

        // prefetch log2(pi) tile in fp16 (consumed after QK — L2 latency hidden)
        uint2 r0 = *(const uint2*)(lpP + k0);
        uint2 r1 = *(const uint2*)(lpP + (size_t)LK + k0);
        uint2 r2 = *(const uint2*)(lpP + (size_t)2 * LK + k0);
        uint2 r3 = *(const uint2*)(lpP + (size_t)3 * LK + k0);

        // stage next K tile into the other buffer
        if (kt < 31 && t < 192) {
            int c = t >> 4, col4 = (t & 15) * 4;
            const float* src = (c < 11)
                ? &g_Kraw[((size_t)b * 11 + c) * LK + k0 + 64 + col4]
                : &g_kc[(size_t)bh * LK + k0 + 64 + col4];
            *(float4*)&Ks[cur ^ 1][c][col4] = *(const float4*)src;
        }

        // ---- QK: S = Qt . k_raw  (inner dim 11), kc folded into first FMA ----
        float S[4][4];
        {
            float4 kc4 = *(const float4*)&Ks[cur][11][tx * 4];
            float kcv[4] = {kc4.x, kc4.y, kc4.z, kc4.w};
            float4 a4 = *(const float4*)&Qs[0][ty * 4];
            float4 b4 = *(const float4*)&Ks[cur][0][tx * 4];
            float av[4] = {a4.x, a4.y, a4.z, a4.w};
            float bw[4] = {b4.x, b4.y, b4.z, b4.w};
            #pragma unroll
            for (int i = 0; i < 4; i++)
                #pragma unroll
                for (int j = 0; j < 4; j++) S[i][j] = av[i] * bw[j] + kcv[j];
        }
        #pragma unroll
        for (int kk = 1; kk < 11; kk++) {
            float4 a4 = *(const float4*)&Qs[kk][ty * 4];
            float4 b4 = *(const float4*)&Ks[cur][kk][tx * 4];
            float av[4] = {a4.x, a4.y, a4.z, a4.w};
            float bw[4] = {b4.x, b4.y, b4.z, b4.w};
            #pragma unroll
            for (int i = 0; i < 4; i++)
                #pragma unroll
                for (int j = 0; j < 4; j++) S[i][j] += av[i] * bw[j];
        }

        // ---- + log2(pi), exp2, accumulate l ----
        {
            float2 p00 = __half22float2(*(__half2*)&r0.x);
            float2 p01 = __half22float2(*(__half2*)&r0.y);
            float2 p10 = __half22float2(*(__half2*)&r1.x);
            float2 p11 = __half22float2(*(__half2*)&r1.y);
            float2 p20 = __half22float2(*(__half2*)&r2.x);
            float2 p21 = __half22float2(*(__half2*)&r2.y);
            float2 p30 = __half22float2(*(__half2*)&r3.x);
            float2 p31 = __half22float2(*(__half2*)&r3.y);
            float pr[4][4] = {{p00.x, p00.y, p01.x, p01.y},
                              {p10.x, p10.y, p11.x, p11.y},
                              {p20.x, p20.y, p21.x, p21.y},
                              {p30.x, p30.y, p31.x, p31.y}};
            #pragma unroll
            for (int i = 0; i < 4; i++) {
                #pragma unroll
                for (int j = 0; j < 4; j++) {
                    S[i][j] = ex2f(S[i][j] + pr[i][j]);
                    l[i] += S[i][j];
                }
            }
        }

        // ---- PV: O += P . v_raw  (V tile == K tile rows 0..10) ----
        #pragma unroll
        for (int c = 0; c < 11; c++) {
            float4 v4 = *(const float4*)&Ks[cur][c][tx * 4];
            float vv[4] = {v4.x, v4.y, v4.z, v4.w};
            #pragma unroll
            for (int i = 0; i < 4; i++) {
                O[i][c] += S[i][0] * vv[0] + S[i][1] * vv[1]
                         + S[i][2] * vv[2] + S[i][3] * vv[3];
            }
        }

        __syncthreads();
    }

    // ---- reduce across the 16 tx lanes, normalize, store ----
    #pragma unroll
    for (int i = 0; i < 4; i++) {
        l[i] += __shfl_xor_sync(0xffffffffu, l[i], 1);
        l[i] += __shfl_xor_sync(0xffffffffu, l[i], 2);
        l[i] += __shfl_xor_sync(0xffffffffu, l[i], 4);
        l[i] += __shfl_xor_sync(0xffffffffu, l[i], 8);
        #pragma unroll
        for (int c = 0; c < 11; c++) {
            O[i][c] += __shfl_xor_sync(0xffffffffu, O[i][c], 1);
            O[i][c] += __shfl_xor_sync(0xffffffffu, O[i][c], 2);
            O[i][c] += __shfl_xor_sync(0xffffffffu, O[i][c], 4);
            O[i][c] += __shfl_xor_sync(0xffffffffu, O[i][c], 8);
        }
    }

    if (tx == 0) {
        #pragma unroll
        for (int i = 0; i < 4; i++) {
            float inv = 1.0f / l[i];
            size_t base = ((size_t)(b * LQ + q0 + ty * 4 + i)) * 88 + h * 11;
            #pragma unroll
            for (int c = 0; c < 11; c++) g_cr[base + c] = O[i][c] * inv;
        }
    }
}

// ---------------- epilogue: out = ctxRaw(4096x88) @ R(88x256) + obias ----------------
__global__ void __launch_bounds__(256)
epilogue_kernel(float* __restrict__ out)
{
    __shared__ float crsT[88][32];
    int t = threadIdx.x;
    int row0 = blockIdx.x * 32;

    for (int i = t; i < 32 * 88; i += 256) {
        int r = i / 88, j = i % 88;
        crsT[j][r] = g_cr[(size_t)(row0 + r) * 88 + j];
    }
    __syncthreads();

    float acc[32];
    #pragma unroll
    for (int r = 0; r < 32; r++) acc[r] = 0.f;

    #pragma unroll 4
    for (int j = 0; j < 88; j++) {
        float rv = g_R[j * HID + t];
        #pragma unroll
        for (int r = 0; r < 32; r += 4) {
            float4 cv = *(const float4*)&crsT[j][r];
            acc[r]     += cv.x * rv;
            acc[r + 1] += cv.y * rv;
            acc[r + 2] += cv.z * rv;
            acc[r + 3] += cv.w * rv;
        }
    }

    float ob = g_obias[t];
    for (int r = 0; r < 32; r++)
        out[(size_t)(row0 + r) * HID + t] = acc[r] + ob;
}

// ---------------- launch ----------------
extern "C" void kernel_launch(void* const* d_in, const int* in_sizes, int n_in,
                              void* d_out, int out_size)
{
    const float* q_fp  = (const float*)d_in[0];
    const float* v_ret = (const float*)d_in[1];
    const float* pi    = (const float*)d_in[2];
    const float* Wq_s  = (const float*)d_in[3];
    const float* bq_s  = (const float*)d_in[4];
    const float* Wk_s  = (const float*)d_in[5];
    const float* bk_s  = (const float*)d_in[6];
    const float* Wq_w  = (const float*)d_in[7];
    const float* bq_w  = (const float*)d_in[8];
    const float* Wk_w  = (const float*)d_in[9];
    const float* bk_w  = (const float*)d_in[10];
    const float* Wv    = (const float*)d_in[11];
    const float* bv    = (const float*)d_in[12];
    const float* Wo    = (const float*)d_in[13];
    const float* bo    = (const float*)d_in[14];
    const float* wb    = (const float*)d_in[15];
    float* out = (float*)d_out;

    p0_params<<<H_ + 1, 256>>>(Wq_s, bq_s, Wk_s, bk_s, Wq_w, bq_w, Wk_w, bk_w,
                               Wv, bv, Wo, bo, wb);
    p1_q<<<(B_ * LQ) / 128, 128>>>(q_fp);
    p1_k<<<(B_ * LK) / 128, 128>>>(v_ret, Wk_w, bk_w, wb);
    p_logpi<<<(B_ * LQ * LK) / 1024, 256>>>(pi);
    dim3 g(H_, LQ / 64, B_);
    attn_kernel<<<g, 256>>>();
    epilogue_kernel<<<(B_ * LQ) / 32, 256>>>(out);
}